// round 13
// baseline (speedup 1.0000x reference)
#include <cuda_runtime.h>
#include <cstdint>

#define BB 8
typedef unsigned long long u64t;

// ------------------------- scratch -------------------------
__device__ float g_bias2[128];               // qt bias || bk
__device__ float g_Bf[8 * 9 * 2 * 64 * 8];   // conv B frags [ch16][t][g][n][kp][s] = 73728
__device__ float g_W2f[2][16 * 128 * 4 * 2]; // 1x1 B frags hi/lo [kk][n][kp][s] = 16384 ea
__device__ float g_msp[BB * 128 * 66 * 68];  // padded tf32-hi mainstream
__device__ float g_msl[BB * 128 * 66 * 68];  // padded tf32-lo residual
__device__ float g_qt[BB * 64 * 4096];       // [b][c][hc][wc]
__device__ float g_vals[BB * 64 * 4096];
__device__ float g_ml[BB * 64 * 64];

// ------------------------- helpers -------------------------
__device__ __forceinline__ float rna(float v) { asm("cvt.rna.tf32.f32 %0, %0;" : "+f"(v)); return v; }
__device__ __forceinline__ uint32_t smem_u32(const void* p) {
    uint32_t a;
    asm("{ .reg .u64 t; cvta.to.shared.u64 t, %1; cvt.u32.u64 %0, t; }" : "=r"(a) : "l"(p));
    return a;
}
__device__ __forceinline__ void cpa16(uint32_t dst, const void* src) {
    asm volatile("cp.async.cg.shared.global [%0], [%1], 16;" :: "r"(dst), "l"(src));
}
__device__ __forceinline__ void cpcommit() { asm volatile("cp.async.commit_group;" ::: "memory"); }
template <int N> __device__ __forceinline__ void cpwait() {
    asm volatile("cp.async.wait_group %0;" :: "n"(N) : "memory");
}
__device__ __forceinline__ void mma_tf32(float* d, uint32_t a0, uint32_t a1, uint32_t a2, uint32_t a3,
                                         uint32_t b0, uint32_t b1) {
    asm volatile(
        "mma.sync.aligned.m16n8k8.row.col.f32.tf32.tf32.f32 "
        "{%0,%1,%2,%3}, {%4,%5,%6,%7}, {%8,%9}, {%0,%1,%2,%3};"
        : "+f"(d[0]), "+f"(d[1]), "+f"(d[2]), "+f"(d[3])
        : "r"(a0), "r"(a1), "r"(a2), "r"(a3), "r"(b0), "r"(b1));
}

// ------------------------- prep_all v2: single prep kernel, vectorized ms split -------------------------
// block ranges: [0,4488) msp/msl x4 | [4488,4616) W2f | 4616 bias2 | [4617,4905) Bf
__global__ void prep_all(const float* __restrict__ ms, const float* __restrict__ Wc,
                         const float* __restrict__ bf, const float* __restrict__ Wf,
                         const float* __restrict__ Wk, const float* __restrict__ bk,
                         const float* __restrict__ Vw) {
    const int bid = blockIdx.x, tid = threadIdx.x;
    if (bid < 4488) {
        int i4 = bid * 256 + tid;      // < 1148928 exactly (= BB*128*66*17)
        int t   = i4 % 17;             // 16B chunk within padded row
        int row = i4 / 17;             // (b*128+f)*66 + hp
        int hp  = row % 66;
        int bf_ = row / 66;
        int h = hp - 1;
        float4 hi4 = make_float4(0.f, 0.f, 0.f, 0.f);
        float4 lo4 = hi4;
        if (h >= 0 && h < 64) {
            const float* src = ms + ((size_t)bf_ * 64 + h) * 64;
            #pragma unroll
            for (int j = 0; j < 4; j++) {
                int w = t * 4 + j - 1;
                if (w >= 0 && w < 64) {
                    float v = src[w];
                    float hv = rna(v);
                    (&hi4.x)[j] = hv;
                    (&lo4.x)[j] = rna(v - hv);
                }
            }
        }
        *(float4*)&g_msp[(size_t)i4 * 4] = hi4;
        *(float4*)&g_msl[(size_t)i4 * 4] = lo4;
    } else if (bid < 4616) {
        int j = (bid - 4488) * 256 + tid;   // < 32768
        int term = j >> 14, jj = j & 16383;
        int s = jj & 1, kp = (jj >> 1) & 3, n = (jj >> 3) & 127, kk = jj >> 10;
        int f = kk * 8 + kp + 4 * s;
        float v;
        if (n < 64) { v = 0.f; for (int d = 0; d < 64; d++) v += Wc[d * 64 + n] * Wf[d * 128 + f]; }
        else v = Wk[(n - 64) * 128 + f];
        float hi = rna(v);
        g_W2f[term][jj] = (term == 0) ? hi : rna(v - hi);
    } else if (bid == 4616) {
        if (tid < 128) {
            int o = tid;
            float bbv;
            if (o < 64) { bbv = 0.f; for (int d = 0; d < 64; d++) bbv += Wc[d * 64 + o] * bf[d]; }
            else bbv = bk[o - 64];
            g_bias2[o] = bbv;
        }
    } else {
        int i = (bid - 4617) * 256 + tid;   // < 73728
        int s = i & 1, kp = (i >> 1) & 3, n = (i >> 3) & 63, g = (i >> 9) & 1;
        int t = (i >> 10) % 9, ch = i / 9216;
        int f = ch * 16 + g * 8 + kp + 4 * s;
        g_Bf[i] = rna(Vw[(size_t)(n * 128 + f) * 9 + t]);
    }
}

// ------------------------- kcoarse2: merged k11t + kconv (unchanged) -------------------------
__global__ void __launch_bounds__(256, 2)
kcoarse2(const float* __restrict__ Vb) {
    extern __shared__ float sm[];
    const int bid = blockIdx.x;
    const int tid = threadIdx.x, wid = tid >> 5, lane = tid & 31;
    const int q = lane >> 2, r = lane & 3;
    uint32_t sb = smem_u32(sm);

    if (bid < 512) {
        // ---------------- 1x1 role ----------------
        const int hc = bid & 63, b = bid >> 6;
        const int w0 = (wid & 3) * 16, wl = w0 + q;
        const int nh = wid >> 2;

        auto stage = [&](int ck) {
            uint32_t base = sb + (ck & 1) * 51200;
            const float* ah = g_msp + ((size_t)(b * 128 + ck * 32) * 66 + hc + 1) * 68;
            const float* al = g_msl + ((size_t)(b * 128 + ck * 32) * 66 + hc + 1) * 68;
            for (int i = tid; i < 544; i += 256) {
                int c4 = i % 17, f = i / 17;
                uint32_t d = base + (f * 72 + c4 * 4) * 4;
                cpa16(d, ah + (size_t)f * 4488 + c4 * 4);
                cpa16(d + 9216, al + (size_t)f * 4488 + c4 * 4);
            }
            const float* bh = g_W2f[0] + ck * 4096;
            const float* bl = g_W2f[1] + ck * 4096;
            uint32_t Bd = base + 18432;
            for (int i = tid; i < 1024; i += 256) {
                cpa16(Bd + i * 16, bh + i * 4);
                cpa16(Bd + 16384 + i * 16, bl + i * 4);
            }
            cpcommit();
        };

        float acc[8][4];
        #pragma unroll
        for (int n0 = 0; n0 < 8; n0++) {
            int c = nh * 64 + n0 * 8 + 2 * r;
            float b0 = g_bias2[c], b1 = g_bias2[c + 1];
            acc[n0][0] = b0; acc[n0][1] = b1; acc[n0][2] = b0; acc[n0][3] = b1;
        }
        stage(0); stage(1);
        for (int ck = 0; ck < 4; ck++) {
            if (ck < 3) cpwait<1>(); else cpwait<0>();
            __syncthreads();
            const float* base = sm + (ck & 1) * 12800;
            const float* Ahi = base;
            const float* Alo = base + 2304;
            const float* Bhi = base + 4608;
            const float* Blo = base + 8704;
            #pragma unroll
            for (int kk = 0; kk < 4; kk++) {
                const float* ah = Ahi + (kk * 8 + r) * 72 + 1 + wl;
                const float* al = Alo + (kk * 8 + r) * 72 + 1 + wl;
                uint32_t h0 = __float_as_uint(ah[0]),   h1 = __float_as_uint(ah[8]);
                uint32_t h2 = __float_as_uint(ah[288]), h3 = __float_as_uint(ah[296]);
                uint32_t l0 = __float_as_uint(al[0]),   l1 = __float_as_uint(al[8]);
                uint32_t l2 = __float_as_uint(al[288]), l3 = __float_as_uint(al[296]);
                const float* bhb = Bhi + (kk * 128 + nh * 64 + q) * 8 + r * 2;
                const float* blb = Blo + (kk * 128 + nh * 64 + q) * 8 + r * 2;
                #pragma unroll
                for (int n0 = 0; n0 < 8; n0++) {
                    float2 bh = *(const float2*)(bhb + n0 * 64);
                    float2 bl = *(const float2*)(blb + n0 * 64);
                    uint32_t bh0 = __float_as_uint(bh.x), bh1 = __float_as_uint(bh.y);
                    mma_tf32(acc[n0], h0, h1, h2, h3, bh0, bh1);
                    mma_tf32(acc[n0], h0, h1, h2, h3, __float_as_uint(bl.x), __float_as_uint(bl.y));
                    mma_tf32(acc[n0], l0, l1, l2, l3, bh0, bh1);
                }
            }
            __syncthreads();
            if (ck + 2 < 4) stage(ck + 2);
        }
        __syncthreads();

        float* s_qk = sm;   // [128][66]
        #pragma unroll
        for (int n0 = 0; n0 < 8; n0++) {
            int c = nh * 64 + n0 * 8 + 2 * r;
            s_qk[c * 66 + wl]           = acc[n0][0];
            s_qk[(c + 1) * 66 + wl]     = acc[n0][1];
            s_qk[c * 66 + wl + 8]       = acc[n0][2];
            s_qk[(c + 1) * 66 + wl + 8] = acc[n0][3];
        }
        if (nh == 0) {
            float* qtb = g_qt + (size_t)b * 64 * 4096 + hc * 64;
            #pragma unroll
            for (int n0 = 0; n0 < 8; n0++) {
                int c = n0 * 8 + 2 * r;
                qtb[(size_t)c * 4096 + wl]           = acc[n0][0];
                qtb[(size_t)(c + 1) * 4096 + wl]     = acc[n0][1];
                qtb[(size_t)c * 4096 + wl + 8]       = acc[n0][2];
                qtb[(size_t)(c + 1) * 4096 + wl + 8] = acc[n0][3];
            }
        }
        __syncthreads();
        if (tid < 64) {
            float s = 0.f;
            #pragma unroll
            for (int c = 0; c < 64; c++) s += s_qk[c * 66 + tid] * s_qk[(64 + c) * 66 + tid];
            g_ml[((size_t)b * 64 + hc) * 64 + tid] = s;
        }
    } else {
        // ---------------- conv role ----------------
        const int blk = bid - 512;
        const int hc0 = (blk & 31) * 2, b = blk >> 5;
        const int px_h = wid >> 2, w0 = (wid & 3) * 16, wl = w0 + q;

        auto stage = [&](int ch) {
            uint32_t slab = sb + (ch & 1) * 55296;
            uint32_t Bd = slab + 18432;
            const float* srcbase = g_msp + ((size_t)(b * 128 + ch * 16) * 66 + hc0) * 68;
            for (int i = tid; i < 1088; i += 256) {
                int c4 = i % 17, row = i / 17;
                int hr = row & 3, f = row >> 2;
                cpa16(slab + (hr * 1152 + f * 72 + c4 * 4) * 4,
                      srcbase + (size_t)f * 4488 + hr * 68 + c4 * 4);
            }
            const float* bsrc = g_Bf + ch * 9216;
            for (int i = tid; i < 2304; i += 256) cpa16(Bd + i * 16, bsrc + i * 4);
            cpcommit();
        };

        float acc[8][4];
        #pragma unroll
        for (int n0 = 0; n0 < 8; n0++) {
            float b0 = Vb[n0 * 8 + 2 * r], b1 = Vb[n0 * 8 + 2 * r + 1];
            acc[n0][0] = b0; acc[n0][1] = b1; acc[n0][2] = b0; acc[n0][3] = b1;
        }
        stage(0); stage(1);
        for (int ch = 0; ch < 8; ch++) {
            if (ch < 7) cpwait<1>(); else cpwait<0>();
            __syncthreads();
            const float* slab = sm + (ch & 1) * 13824;
            const float* Bd = slab + 4608;
            #pragma unroll
            for (int t = 0; t < 9; t++) {
                const int ky = t / 3, kx = t % 3;
                const float* Ab = slab + (px_h + ky) * 1152 + wl + kx;
                #pragma unroll
                for (int g = 0; g < 2; g++) {
                    const float* Af = Ab + (g * 8 + r) * 72;
                    uint32_t a0 = __float_as_uint(Af[0]);
                    uint32_t a1 = __float_as_uint(Af[8]);
                    uint32_t a2 = __float_as_uint(Af[288]);
                    uint32_t a3 = __float_as_uint(Af[296]);
                    const float* bb = Bd + ((t * 2 + g) * 64 + q) * 8 + r * 2;
                    #pragma unroll
                    for (int n0 = 0; n0 < 8; n0++) {
                        float2 bv = *(const float2*)(bb + n0 * 64);
                        mma_tf32(acc[n0], a0, a1, a2, a3,
                                 __float_as_uint(bv.x), __float_as_uint(bv.y));
                    }
                }
            }
            __syncthreads();
            if (ch + 2 < 8) stage(ch + 2);
        }

        const int h = hc0 + px_h;
        float* vbase = g_vals + (size_t)b * 64 * 4096 + h * 64;
        #pragma unroll
        for (int n0 = 0; n0 < 8; n0++) {
            int c = n0 * 8 + 2 * r;
            float* p0 = vbase + (size_t)c * 4096;
            float* p1 = p0 + 4096;
            p0[wl]     = acc[n0][0];
            p1[wl]     = acc[n0][1];
            p0[wl + 8] = acc[n0][2];
            p1[wl + 8] = acc[n0][3];
        }
    }
}

// ------------------------- kfine5: 512-thread float2 streaming fine pass -------------------------
// grid (2 wt, 128 h, 8 b), 512 thr. warp = 64 consecutive w (float2/lane); warp id = 4-ch group.
__global__ void __launch_bounds__(512)
kfine5(const float* __restrict__ ctx, float* __restrict__ out) {
    __shared__ float2 s_p[3][16][33];
    const int b = blockIdx.z, h = blockIdx.y;
    const int cg = threadIdx.x >> 5, lane = threadIdx.x & 31;
    const int w2 = blockIdx.x * 64 + lane * 2;
    const int c0 = cg * 4;
    const int hc = h >> 1, wc = w2 >> 1;

    const float* cb = ctx + ((size_t)(b * 3) * 64 + c0) * 16384 + h * 128 + w2;
    float2 r0[4], r1[4], r2[4];
    #pragma unroll
    for (int i = 0; i < 4; i++) {
        r0[i] = __ldcs((const float2*)(cb + (size_t)i * 16384));
        r1[i] = __ldcs((const float2*)(cb + (size_t)(64 + i) * 16384));
        r2[i] = __ldcs((const float2*)(cb + (size_t)(128 + i) * 16384));
    }
    float l3 = g_ml[((size_t)b * 64 + hc) * 64 + wc];
    const float* qb = g_qt + ((size_t)b * 64 + c0) * 4096 + hc * 64 + wc;
    float2 p0 = make_float2(0.f, 0.f), p1 = p0, p2 = p0;
    #pragma unroll
    for (int i = 0; i < 4; i++) {
        float qv = qb[(size_t)i * 4096];
        p0.x += r0[i].x * qv; p0.y += r0[i].y * qv;
        p1.x += r1[i].x * qv; p1.y += r1[i].y * qv;
        p2.x += r2[i].x * qv; p2.y += r2[i].y * qv;
    }
    s_p[0][cg][lane] = p0; s_p[1][cg][lane] = p1; s_p[2][cg][lane] = p2;
    __syncthreads();
    float2 l0 = make_float2(0.f, 0.f), l1 = l0, l2 = l0;
    #pragma unroll
    for (int g = 0; g < 16; g++) {
        float2 t0 = s_p[0][g][lane], t1 = s_p[1][g][lane], t2 = s_p[2][g][lane];
        l0.x += t0.x; l0.y += t0.y;
        l1.x += t1.x; l1.y += t1.y;
        l2.x += t2.x; l2.y += t2.y;
    }

    float mxx = fmaxf(fmaxf(l0.x, l1.x), fmaxf(l2.x, l3));
    float e0x = __expf(l0.x - mxx), e1x = __expf(l1.x - mxx), e2x = __expf(l2.x - mxx), e3x = __expf(l3 - mxx);
    float invx = 1.f / (e0x + e1x + e2x + e3x);
    float a0x = e0x * invx, a1x = e1x * invx, a2x = e2x * invx, a3x = e3x * invx;

    float mxy = fmaxf(fmaxf(l0.y, l1.y), fmaxf(l2.y, l3));
    float e0y = __expf(l0.y - mxy), e1y = __expf(l1.y - mxy), e2y = __expf(l2.y - mxy), e3y = __expf(l3 - mxy);
    float invy = 1.f / (e0y + e1y + e2y + e3y);
    float a0y = e0y * invy, a1y = e1y * invy, a2y = e2y * invy, a3y = e3y * invy;

    const float* vb = g_vals + ((size_t)b * 64 + c0) * 4096 + hc * 64 + wc;
    float* ob = out + ((size_t)b * 64 + c0) * 16384 + h * 128 + w2;
    #pragma unroll
    for (int i = 0; i < 4; i++) {
        float v = vb[(size_t)i * 4096];
        float2 o;
        o.x = r0[i].x * a0x + r1[i].x * a1x + r2[i].x * a2x + v * a3x;
        o.y = r0[i].y * a0y + r1[i].y * a1y + r2[i].y * a2y + v * a3y;
        __stcs((float2*)(ob + (size_t)i * 16384), o);
    }
}

// ------------------------- launch -------------------------
extern "C" void kernel_launch(void* const* d_in, const int* in_sizes, int n_in,
                              void* d_out, int out_size) {
    const float* contexts   = (const float*)d_in[0];
    const float* mainstream = (const float*)d_in[1];
    const float* Wc = (const float*)d_in[2];
    // d_in[3] = bc: softmax-invariant, unused
    const float* Wf = (const float*)d_in[4];
    const float* bf = (const float*)d_in[5];
    const float* Wk = (const float*)d_in[6];
    const float* bk = (const float*)d_in[7];
    const float* Vw = (const float*)d_in[8];
    const float* Vb = (const float*)d_in[9];

    cudaFuncSetAttribute(kcoarse2, cudaFuncAttributeMaxDynamicSharedMemorySize, 110592);

    prep_all<<<4905, 256>>>(mainstream, Wc, bf, Wf, Wk, bk, Vw);
    kcoarse2<<<768, 256, 110592>>>(Vb);
    kfine5<<<dim3(2, 128, 8), 512>>>(contexts, (float*)d_out);
}

// round 15
// speedup vs baseline: 1.4425x; 1.4425x over previous
#include <cuda_runtime.h>
#include <cstdint>

#define BB 8
typedef unsigned long long u64t;

// ------------------------- scratch -------------------------
__device__ float g_bias2[128];               // qt bias || bk
__device__ float g_Bf[8 * 9 * 2 * 64 * 8];   // conv B frags [ch16][t][g][n][kp][s] = 73728
__device__ float g_W2f[2][16 * 128 * 4 * 2]; // 1x1 B frags hi/lo [kk][n][kp][s] = 16384 ea
__device__ float g_msp[BB * 128 * 66 * 68];  // padded tf32-hi mainstream
__device__ float g_msl[BB * 128 * 66 * 68];  // padded tf32-lo residual
__device__ float g_qt[BB * 64 * 4096];       // [b][c][hc][wc]
__device__ float g_vals[BB * 64 * 4096];
__device__ float g_ml[BB * 64 * 64];

// ------------------------- helpers -------------------------
__device__ __forceinline__ float rna(float v) { asm("cvt.rna.tf32.f32 %0, %0;" : "+f"(v)); return v; }
__device__ __forceinline__ uint32_t smem_u32(const void* p) {
    uint32_t a;
    asm("{ .reg .u64 t; cvta.to.shared.u64 t, %1; cvt.u32.u64 %0, t; }" : "=r"(a) : "l"(p));
    return a;
}
__device__ __forceinline__ void cpa16(uint32_t dst, const void* src) {
    asm volatile("cp.async.cg.shared.global [%0], [%1], 16;" :: "r"(dst), "l"(src));
}
__device__ __forceinline__ void cpcommit() { asm volatile("cp.async.commit_group;" ::: "memory"); }
template <int N> __device__ __forceinline__ void cpwait() {
    asm volatile("cp.async.wait_group %0;" :: "n"(N) : "memory");
}
__device__ __forceinline__ void mma_tf32(float* d, uint32_t a0, uint32_t a1, uint32_t a2, uint32_t a3,
                                         uint32_t b0, uint32_t b1) {
    asm volatile(
        "mma.sync.aligned.m16n8k8.row.col.f32.tf32.tf32.f32 "
        "{%0,%1,%2,%3}, {%4,%5,%6,%7}, {%8,%9}, {%0,%1,%2,%3};"
        : "+f"(d[0]), "+f"(d[1]), "+f"(d[2]), "+f"(d[3])
        : "r"(a0), "r"(a1), "r"(a2), "r"(a3), "r"(b0), "r"(b1));
}

// ------------------------- prep_all v2: single prep kernel, vectorized ms split -------------------------
// block ranges: [0,4488) msp/msl x4 | [4488,4616) W2f | 4616 bias2 | [4617,4905) Bf
__global__ void prep_all(const float* __restrict__ ms, const float* __restrict__ Wc,
                         const float* __restrict__ bf, const float* __restrict__ Wf,
                         const float* __restrict__ Wk, const float* __restrict__ bk,
                         const float* __restrict__ Vw) {
    const int bid = blockIdx.x, tid = threadIdx.x;
    if (bid < 4488) {
        int i4 = bid * 256 + tid;      // < 1148928 exactly (= BB*128*66*17)
        int t   = i4 % 17;             // 16B chunk within padded row
        int row = i4 / 17;             // (b*128+f)*66 + hp
        int hp  = row % 66;
        int bf_ = row / 66;
        int h = hp - 1;
        float4 hi4 = make_float4(0.f, 0.f, 0.f, 0.f);
        float4 lo4 = hi4;
        if (h >= 0 && h < 64) {
            const float* src = ms + ((size_t)bf_ * 64 + h) * 64;
            #pragma unroll
            for (int j = 0; j < 4; j++) {
                int w = t * 4 + j - 1;
                if (w >= 0 && w < 64) {
                    float v = src[w];
                    float hv = rna(v);
                    (&hi4.x)[j] = hv;
                    (&lo4.x)[j] = rna(v - hv);
                }
            }
        }
        *(float4*)&g_msp[(size_t)i4 * 4] = hi4;
        *(float4*)&g_msl[(size_t)i4 * 4] = lo4;
    } else if (bid < 4616) {
        int j = (bid - 4488) * 256 + tid;   // < 32768
        int term = j >> 14, jj = j & 16383;
        int s = jj & 1, kp = (jj >> 1) & 3, n = (jj >> 3) & 127, kk = jj >> 10;
        int f = kk * 8 + kp + 4 * s;
        float v;
        if (n < 64) { v = 0.f; for (int d = 0; d < 64; d++) v += Wc[d * 64 + n] * Wf[d * 128 + f]; }
        else v = Wk[(n - 64) * 128 + f];
        float hi = rna(v);
        g_W2f[term][jj] = (term == 0) ? hi : rna(v - hi);
    } else if (bid == 4616) {
        if (tid < 128) {
            int o = tid;
            float bbv;
            if (o < 64) { bbv = 0.f; for (int d = 0; d < 64; d++) bbv += Wc[d * 64 + o] * bf[d]; }
            else bbv = bk[o - 64];
            g_bias2[o] = bbv;
        }
    } else {
        int i = (bid - 4617) * 256 + tid;   // < 73728
        int s = i & 1, kp = (i >> 1) & 3, n = (i >> 3) & 63, g = (i >> 9) & 1;
        int t = (i >> 10) % 9, ch = i / 9216;
        int f = ch * 16 + g * 8 + kp + 4 * s;
        g_Bf[i] = rna(Vw[(size_t)(n * 128 + f) * 9 + t]);
    }
}

// ------------------------- kcoarse2: merged k11t + kconv (round-12 proven, unchanged) -------------------------
__global__ void __launch_bounds__(256, 2)
kcoarse2(const float* __restrict__ Vb) {
    extern __shared__ float sm[];
    const int bid = blockIdx.x;
    const int tid = threadIdx.x, wid = tid >> 5, lane = tid & 31;
    const int q = lane >> 2, r = lane & 3;
    uint32_t sb = smem_u32(sm);

    if (bid < 512) {
        // ---------------- 1x1 role ----------------
        const int hc = bid & 63, b = bid >> 6;
        const int w0 = (wid & 3) * 16, wl = w0 + q;
        const int nh = wid >> 2;

        auto stage = [&](int ck) {
            uint32_t base = sb + (ck & 1) * 51200;
            const float* ah = g_msp + ((size_t)(b * 128 + ck * 32) * 66 + hc + 1) * 68;
            const float* al = g_msl + ((size_t)(b * 128 + ck * 32) * 66 + hc + 1) * 68;
            for (int i = tid; i < 544; i += 256) {
                int c4 = i % 17, f = i / 17;
                uint32_t d = base + (f * 72 + c4 * 4) * 4;
                cpa16(d, ah + (size_t)f * 4488 + c4 * 4);
                cpa16(d + 9216, al + (size_t)f * 4488 + c4 * 4);
            }
            const float* bh = g_W2f[0] + ck * 4096;
            const float* bl = g_W2f[1] + ck * 4096;
            uint32_t Bd = base + 18432;
            for (int i = tid; i < 1024; i += 256) {
                cpa16(Bd + i * 16, bh + i * 4);
                cpa16(Bd + 16384 + i * 16, bl + i * 4);
            }
            cpcommit();
        };

        float acc[8][4];
        #pragma unroll
        for (int n0 = 0; n0 < 8; n0++) {
            int c = nh * 64 + n0 * 8 + 2 * r;
            float b0 = g_bias2[c], b1 = g_bias2[c + 1];
            acc[n0][0] = b0; acc[n0][1] = b1; acc[n0][2] = b0; acc[n0][3] = b1;
        }
        stage(0); stage(1);
        for (int ck = 0; ck < 4; ck++) {
            if (ck < 3) cpwait<1>(); else cpwait<0>();
            __syncthreads();
            const float* base = sm + (ck & 1) * 12800;
            const float* Ahi = base;
            const float* Alo = base + 2304;
            const float* Bhi = base + 4608;
            const float* Blo = base + 8704;
            #pragma unroll
            for (int kk = 0; kk < 4; kk++) {
                const float* ah = Ahi + (kk * 8 + r) * 72 + 1 + wl;
                const float* al = Alo + (kk * 8 + r) * 72 + 1 + wl;
                uint32_t h0 = __float_as_uint(ah[0]),   h1 = __float_as_uint(ah[8]);
                uint32_t h2 = __float_as_uint(ah[288]), h3 = __float_as_uint(ah[296]);
                uint32_t l0 = __float_as_uint(al[0]),   l1 = __float_as_uint(al[8]);
                uint32_t l2 = __float_as_uint(al[288]), l3 = __float_as_uint(al[296]);
                const float* bhb = Bhi + (kk * 128 + nh * 64 + q) * 8 + r * 2;
                const float* blb = Blo + (kk * 128 + nh * 64 + q) * 8 + r * 2;
                #pragma unroll
                for (int n0 = 0; n0 < 8; n0++) {
                    float2 bh = *(const float2*)(bhb + n0 * 64);
                    float2 bl = *(const float2*)(blb + n0 * 64);
                    uint32_t bh0 = __float_as_uint(bh.x), bh1 = __float_as_uint(bh.y);
                    mma_tf32(acc[n0], h0, h1, h2, h3, bh0, bh1);
                    mma_tf32(acc[n0], h0, h1, h2, h3, __float_as_uint(bl.x), __float_as_uint(bl.y));
                    mma_tf32(acc[n0], l0, l1, l2, l3, bh0, bh1);
                }
            }
            __syncthreads();
            if (ck + 2 < 4) stage(ck + 2);
        }
        __syncthreads();

        float* s_qk = sm;   // [128][66]
        #pragma unroll
        for (int n0 = 0; n0 < 8; n0++) {
            int c = nh * 64 + n0 * 8 + 2 * r;
            s_qk[c * 66 + wl]           = acc[n0][0];
            s_qk[(c + 1) * 66 + wl]     = acc[n0][1];
            s_qk[c * 66 + wl + 8]       = acc[n0][2];
            s_qk[(c + 1) * 66 + wl + 8] = acc[n0][3];
        }
        if (nh == 0) {
            float* qtb = g_qt + (size_t)b * 64 * 4096 + hc * 64;
            #pragma unroll
            for (int n0 = 0; n0 < 8; n0++) {
                int c = n0 * 8 + 2 * r;
                qtb[(size_t)c * 4096 + wl]           = acc[n0][0];
                qtb[(size_t)(c + 1) * 4096 + wl]     = acc[n0][1];
                qtb[(size_t)c * 4096 + wl + 8]       = acc[n0][2];
                qtb[(size_t)(c + 1) * 4096 + wl + 8] = acc[n0][3];
            }
        }
        __syncthreads();
        if (tid < 64) {
            float s = 0.f;
            #pragma unroll
            for (int c = 0; c < 64; c++) s += s_qk[c * 66 + tid] * s_qk[(64 + c) * 66 + tid];
            g_ml[((size_t)b * 64 + hc) * 64 + tid] = s;
        }
    } else {
        // ---------------- conv role ----------------
        const int blk = bid - 512;
        const int hc0 = (blk & 31) * 2, b = blk >> 5;
        const int px_h = wid >> 2, w0 = (wid & 3) * 16, wl = w0 + q;

        auto stage = [&](int ch) {
            uint32_t slab = sb + (ch & 1) * 55296;
            uint32_t Bd = slab + 18432;
            const float* srcbase = g_msp + ((size_t)(b * 128 + ch * 16) * 66 + hc0) * 68;
            for (int i = tid; i < 1088; i += 256) {
                int c4 = i % 17, row = i / 17;
                int hr = row & 3, f = row >> 2;
                cpa16(slab + (hr * 1152 + f * 72 + c4 * 4) * 4,
                      srcbase + (size_t)f * 4488 + hr * 68 + c4 * 4);
            }
            const float* bsrc = g_Bf + ch * 9216;
            for (int i = tid; i < 2304; i += 256) cpa16(Bd + i * 16, bsrc + i * 4);
            cpcommit();
        };

        float acc[8][4];
        #pragma unroll
        for (int n0 = 0; n0 < 8; n0++) {
            float b0 = Vb[n0 * 8 + 2 * r], b1 = Vb[n0 * 8 + 2 * r + 1];
            acc[n0][0] = b0; acc[n0][1] = b1; acc[n0][2] = b0; acc[n0][3] = b1;
        }
        stage(0); stage(1);
        for (int ch = 0; ch < 8; ch++) {
            if (ch < 7) cpwait<1>(); else cpwait<0>();
            __syncthreads();
            const float* slab = sm + (ch & 1) * 13824;
            const float* Bd = slab + 4608;
            #pragma unroll
            for (int t = 0; t < 9; t++) {
                const int ky = t / 3, kx = t % 3;
                const float* Ab = slab + (px_h + ky) * 1152 + wl + kx;
                #pragma unroll
                for (int g = 0; g < 2; g++) {
                    const float* Af = Ab + (g * 8 + r) * 72;
                    uint32_t a0 = __float_as_uint(Af[0]);
                    uint32_t a1 = __float_as_uint(Af[8]);
                    uint32_t a2 = __float_as_uint(Af[288]);
                    uint32_t a3 = __float_as_uint(Af[296]);
                    const float* bb = Bd + ((t * 2 + g) * 64 + q) * 8 + r * 2;
                    #pragma unroll
                    for (int n0 = 0; n0 < 8; n0++) {
                        float2 bv = *(const float2*)(bb + n0 * 64);
                        mma_tf32(acc[n0], a0, a1, a2, a3,
                                 __float_as_uint(bv.x), __float_as_uint(bv.y));
                    }
                }
            }
            __syncthreads();
            if (ch + 2 < 8) stage(ch + 2);
        }

        const int h = hc0 + px_h;
        float* vbase = g_vals + (size_t)b * 64 * 4096 + h * 64;
        #pragma unroll
        for (int n0 = 0; n0 < 8; n0++) {
            int c = n0 * 8 + 2 * r;
            float* p0 = vbase + (size_t)c * 4096;
            float* p1 = p0 + 4096;
            p0[wl]     = acc[n0][0];
            p1[wl]     = acc[n0][1];
            p0[wl + 8] = acc[n0][2];
            p1[wl + 8] = acc[n0][3];
        }
    }
}

// ------------------------- kfine4: float2 streaming fine pass (round-12 proven shape) -------------------------
// grid (4 wt, 128 h, 8 b), 256 thr. warp = 32 consecutive w (float2/lane); warp id = 8-ch group.
__global__ void __launch_bounds__(256)
kfine4(const float* __restrict__ ctx, float* __restrict__ out) {
    __shared__ float2 s_p[3][8][17];
    const int b = blockIdx.z, h = blockIdx.y;
    const int cg = threadIdx.x >> 5, lane = threadIdx.x & 31;
    const int w2 = blockIdx.x * 32 + (lane & 15) * 2;
    const int half = lane >> 4;       // unused for addressing width; lanes 0-15 / 16-31 same w range? no:
    // NOTE: keep the round-12 addressing exactly: 64 w per block, lane*2.
    (void)half;
    const int w2r = blockIdx.x * 32; (void)w2r;
    const int w2full = blockIdx.x * 32 + (lane & 15) * 2; (void)w2full;
    // Reverting to exact round-12 logic with grid.x=4 requires 32 w per block:
    // lanes 0..15 cover w2 = gx*32 + [0..30], lanes 16..31 duplicate -> wrong.
    // Use 16 lanes x float2 = 32 w: split warp into two half-warps covering ctx0/1? Simpler:
    // fall back to grid.x = 2 with lane*2 (exact round-12 kernel).
    const int w2b = (blockIdx.x >> 1) * 64 + lane * 2 + (blockIdx.x & 1) * 0;
    (void)w2b;
    // ---- exact round-12 body ----
    const int W2 = blockIdx.x * 64 + lane * 2;
    const int c0 = cg * 8;
    const int hc = h >> 1, wc = W2 >> 1;

    const float* cb = ctx + ((size_t)(b * 3) * 64 + c0) * 16384 + h * 128 + W2;
    float2 r0[8], r1[8], r2[8];
    #pragma unroll
    for (int i = 0; i < 8; i++) {
        r0[i] = __ldcs((const float2*)(cb + (size_t)i * 16384));
        r1[i] = __ldcs((const float2*)(cb + (size_t)(64 + i) * 16384));
        r2[i] = __ldcs((const float2*)(cb + (size_t)(128 + i) * 16384));
    }
    const float* qb = g_qt + ((size_t)b * 64 + c0) * 4096 + hc * 64 + wc;
    float2 p0 = make_float2(0.f, 0.f), p1 = p0, p2 = p0;
    #pragma unroll
    for (int i = 0; i < 8; i++) {
        float qv = qb[(size_t)i * 4096];
        p0.x += r0[i].x * qv; p0.y += r0[i].y * qv;
        p1.x += r1[i].x * qv; p1.y += r1[i].y * qv;
        p2.x += r2[i].x * qv; p2.y += r2[i].y * qv;
    }
    __shared__ float2 s_q[3][8][33];
    s_q[0][cg][lane] = p0; s_q[1][cg][lane] = p1; s_q[2][cg][lane] = p2;
    __syncthreads();
    float2 l0 = make_float2(0.f, 0.f), l1 = l0, l2 = l0;
    #pragma unroll
    for (int g = 0; g < 8; g++) {
        float2 t0 = s_q[0][g][lane], t1 = s_q[1][g][lane], t2 = s_q[2][g][lane];
        l0.x += t0.x; l0.y += t0.y;
        l1.x += t1.x; l1.y += t1.y;
        l2.x += t2.x; l2.y += t2.y;
    }
    float l3 = g_ml[((size_t)b * 64 + hc) * 64 + wc];

    float mxx = fmaxf(fmaxf(l0.x, l1.x), fmaxf(l2.x, l3));
    float e0x = __expf(l0.x - mxx), e1x = __expf(l1.x - mxx), e2x = __expf(l2.x - mxx), e3x = __expf(l3 - mxx);
    float invx = 1.f / (e0x + e1x + e2x + e3x);
    float a0x = e0x * invx, a1x = e1x * invx, a2x = e2x * invx, a3x = e3x * invx;

    float mxy = fmaxf(fmaxf(l0.y, l1.y), fmaxf(l2.y, l3));
    float e0y = __expf(l0.y - mxy), e1y = __expf(l1.y - mxy), e2y = __expf(l2.y - mxy), e3y = __expf(l3 - mxy);
    float invy = 1.f / (e0y + e1y + e2y + e3y);
    float a0y = e0y * invy, a1y = e1y * invy, a2y = e2y * invy, a3y = e3y * invy;

    const float* vb = g_vals + ((size_t)b * 64 + c0) * 4096 + hc * 64 + wc;
    float* ob = out + ((size_t)b * 64 + c0) * 16384 + h * 128 + W2;
    #pragma unroll
    for (int i = 0; i < 8; i++) {
        float v = vb[(size_t)i * 4096];
        float2 o;
        o.x = r0[i].x * a0x + r1[i].x * a1x + r2[i].x * a2x + v * a3x;
        o.y = r0[i].y * a0y + r1[i].y * a1y + r2[i].y * a2y + v * a3y;
        __stcs((float2*)(ob + (size_t)i * 16384), o);
    }
}

// ------------------------- launch -------------------------
extern "C" void kernel_launch(void* const* d_in, const int* in_sizes, int n_in,
                              void* d_out, int out_size) {
    const float* contexts   = (const float*)d_in[0];
    const float* mainstream = (const float*)d_in[1];
    const float* Wc = (const float*)d_in[2];
    // d_in[3] = bc: softmax-invariant, unused
    const float* Wf = (const float*)d_in[4];
    const float* bf = (const float*)d_in[5];
    const float* Wk = (const float*)d_in[6];
    const float* bk = (const float*)d_in[7];
    const float* Vw = (const float*)d_in[8];
    const float* Vb = (const float*)d_in[9];

    cudaFuncSetAttribute(kcoarse2, cudaFuncAttributeMaxDynamicSharedMemorySize, 110592);

    prep_all<<<4905, 256>>>(mainstream, Wc, bf, Wf, Wk, bk, Vw);
    kcoarse2<<<768, 256, 110592>>>(Vb);
    kfine4<<<dim3(2, 128, 8), 256>>>(contexts, (float*)d_out);
}